// round 4
// baseline (speedup 1.0000x reference)
#include <cuda_runtime.h>
#include <cstdint>
#include <math.h>

#define T_STEPS 2048
#define BATCH   512
#define DIM     128
#define HID     128
#define NG      32          // 4 gates * 8 wires
// smem: Xs(128*132) | Ws(32*128) | bs(32) | sPC(128) | sPS(128)
#define GEMM_SMEM_FLOATS (128*132 + 32*128 + 32 + 128 + 128)
#define GEMM_SMEM_BYTES  (GEMM_SMEM_FLOATS * 4)

// poly coeffs A[row][gate][8], compact h-chain g_S[(T+1)*B]
__device__ float g_A[(size_t)T_STEPS * BATCH * NG];
__device__ float g_S[(size_t)(T_STEPS + 1) * BATCH];
__device__ float g_whsum[NG];
__device__ float g_PC[4][8][4];   // [jj][w][g] coeff of cos(z_w) in a_{2jj}
__device__ float g_PS[4][8][4];   // [jj][w][g] coeff of sin(z_w) in a_{2jj+1}

typedef unsigned long long u64;

__device__ __forceinline__ float tanh_fast(float x) {
    float r; asm("tanh.approx.f32 %0, %1;" : "=f"(r) : "f"(x)); return r;
}
__device__ __forceinline__ u64 ffma2(u64 a, u64 b, u64 c) {
    u64 d; asm("fma.rn.f32x2 %0, %1, %2, %3;" : "=l"(d) : "l"(a), "l"(b), "l"(c));
    return d;
}

// ---------------- init: whsum + Lagrange-on-Chebyshev coefficient tables ----------------
// q*sc interpolated as degree-7 poly in s on [-0.75, 0.75] (|h| <= sigmoid(1) = 0.731).
// q*sc = off - m*sum_w [cos(z_w)cos(whs_w s) - sin(z_w)sin(whs_w s)]; node symmetry
// makes cos-terms even monomials only, sin-terms odd only.
__global__ void init_kernel(const float* __restrict__ Wf, const float* __restrict__ Wi,
                            const float* __restrict__ Wu, const float* __restrict__ Wo) {
    __shared__ double sL[8][8];        // [node k][monomial j]
    const int n = threadIdx.x;         // 0..31
    const int g = n >> 3, w = n & 7;
    const float* W = (g == 0) ? Wf : (g == 1) ? Wi : (g == 2) ? Wu : Wo;
    float s = 0.f;
#pragma unroll
    for (int k = 0; k < 128; k++) s += W[w * 256 + 128 + k];
    g_whsum[n] = s;

    double xk[8];
#pragma unroll
    for (int k = 0; k < 8; k++) xk[k] = 0.75 * cos((2.0 * k + 1.0) * M_PI / 16.0);

    if (n < 8) {   // Lagrange basis L_n -> monomial coeffs (double)
        double cf[8];
        for (int i = 0; i < 8; i++) cf[i] = 0.0;
        cf[0] = 1.0;
        double den = 1.0;
        int deg = 0;
        for (int j = 0; j < 8; j++) {
            if (j == n) continue;
            for (int i = deg + 1; i >= 1; i--) cf[i] = cf[i - 1] - xk[j] * cf[i];
            cf[0] = -xk[j] * cf[0];
            deg++;
            den *= (xk[n] - xk[j]);
        }
        for (int j = 0; j < 8; j++) sL[n][j] = cf[j] / den;
    }
    __syncthreads();

    const double m = (g == 2) ? (1.0 / 16.0) : (1.0 / 32.0);
    for (int jj = 0; jj < 4; jj++) {
        double pc = 0.0, ps = 0.0;
        for (int k = 0; k < 8; k++) {
            double th = (double)s * xk[k];
            pc += sL[k][2 * jj]     * cos(th);
            ps += sL[k][2 * jj + 1] * sin(th);
        }
        g_PC[jj][w][g] = (float)(-m * pc);
        g_PS[jj][w][g] = (float)( m * ps);
    }
}

// ---------------- GEMM + fused eval: X -> Z -> poly coefficients A ----------------
// M = T*B rows, N = 32, K = 128. 128-row tiles, 256 threads, ffma2 mainloop.
__global__ void __launch_bounds__(256, 2) gemm_kernel(
    const float* __restrict__ X,
    const float* __restrict__ Wf, const float* __restrict__ bf,
    const float* __restrict__ Wi, const float* __restrict__ bi,
    const float* __restrict__ Wu, const float* __restrict__ bu,
    const float* __restrict__ Wo, const float* __restrict__ bo) {
    extern __shared__ float sm[];
    float* Xs  = sm;                       // [128][132]
    float* Ws  = sm + 128 * 132;           // [32][128]
    float* bs  = Ws + 32 * 128;            // [32]
    float* sPC = bs + 32;                  // [4][8][4]
    float* sPS = sPC + 128;                // [4][8][4]
    float* Zs  = sm;                       // reuse Xs region, pitch 36 (4608 floats)
    float* As  = sm + 4608;                // second half of Xs region, pitch 36
    const int tid = threadIdx.x;
    const size_t m0 = (size_t)blockIdx.x * 128;

    if (tid < 128)      sPC[tid] = ((const float*)g_PC)[tid];
    else                sPS[tid - 128] = ((const float*)g_PS)[tid - 128];

#pragma unroll
    for (int i = 0; i < 16; i++) {
        int idx = tid + i * 256;
        int n = idx >> 7, k = idx & 127;
        int g = n >> 3, w = n & 7;
        const float* W = (g == 0) ? Wf : (g == 1) ? Wi : (g == 2) ? Wu : Wo;
        Ws[n * 128 + k] = W[w * 256 + k];
    }
    if (tid < 32) {
        int g = tid >> 3, w = tid & 7;
        const float* bb = (g == 0) ? bf : (g == 1) ? bi : (g == 2) ? bu : bo;
        bs[tid] = bb[w];
    }
#pragma unroll
    for (int i = 0; i < 16; i++) {
        int idx = tid + i * 256;
        int m = idx >> 5, j = idx & 31;
        float4 v = *(const float4*)(X + (m0 + m) * 128 + j * 4);
        *(float4*)(Xs + m * 132 + j * 4) = v;
    }
    __syncthreads();

    const int lane = tid & 31;
    const int n0 = (tid >> 5) * 4;
    ulonglong2 acc[4][4];
#pragma unroll
    for (int j = 0; j < 4; j++)
#pragma unroll
        for (int i = 0; i < 4; i++) { acc[j][i].x = 0ull; acc[j][i].y = 0ull; }

#pragma unroll 4
    for (int k = 0; k < 128; k += 4) {
        ulonglong2 A[4], Bv[4];
#pragma unroll
        for (int j = 0; j < 4; j++)
            A[j] = *(const ulonglong2*)(Xs + (lane + 32 * j) * 132 + k);
#pragma unroll
        for (int i = 0; i < 4; i++)
            Bv[i] = *(const ulonglong2*)(Ws + (n0 + i) * 128 + k);
#pragma unroll
        for (int j = 0; j < 4; j++)
#pragma unroll
            for (int i = 0; i < 4; i++) {
                acc[j][i].x = ffma2(A[j].x, Bv[i].x, acc[j][i].x);
                acc[j][i].y = ffma2(A[j].y, Bv[i].y, acc[j][i].y);
            }
    }
    __syncthreads();
    // stage Z (with bias) into Zs, pitch 36
#pragma unroll
    for (int j = 0; j < 4; j++)
#pragma unroll
        for (int i = 0; i < 4; i++) {
            float2 lo = *(float2*)&acc[j][i].x;
            float2 hi = *(float2*)&acc[j][i].y;
            Zs[(lane + 32 * j) * 36 + n0 + i] = (lo.x + lo.y) + (hi.x + hi.y) + bs[n0 + i];
        }
    __syncthreads();

    // fused eval: thread -> (gate g, rows r0, r0+1)
    {
        const int g = tid & 3;
        const int r0 = (tid >> 2) * 2;
        const float off = (g == 2) ? 0.5f : 0.25f;
#pragma unroll
        for (int rr = 0; rr < 2; rr++) {
            const int r = r0 + rr;
            float ca[8], sa[8];
#pragma unroll
            for (int w = 0; w < 8; w++) {
                float z = Zs[r * 36 + g * 8 + w];
                ca[w] = __cosf(z); sa[w] = __sinf(z);
            }
            float ae[4] = {off, 0.f, 0.f, 0.f}, ao[4] = {0.f, 0.f, 0.f, 0.f};
#pragma unroll
            for (int w = 0; w < 8; w++)
#pragma unroll
                for (int jj = 0; jj < 4; jj++) {
                    ae[jj] = fmaf(ca[w], sPC[(jj * 8 + w) * 4 + g], ae[jj]);
                    ao[jj] = fmaf(sa[w], sPS[(jj * 8 + w) * 4 + g], ao[jj]);
                }
            float4* dst = (float4*)(As + r * 36 + g * 8);
            dst[0] = make_float4(ae[0], ao[0], ae[1], ao[1]);
            dst[1] = make_float4(ae[2], ao[2], ae[3], ao[3]);
        }
    }
    __syncthreads();
    // coalesced store As -> g_A
#pragma unroll
    for (int i = 0; i < 4; i++) {
        int idx = tid + i * 256;       // 0..1023 float4s
        int m = idx >> 3, q = idx & 7;
        float4 v = *(const float4*)(As + m * 36 + q * 4);
        *(float4*)(g_A + (m0 + m) * 32 + q * 4) = v;
    }
}

// ---------------- rnn: one warp per chain; compact scalar output only ----------------
__global__ void __launch_bounds__(32) rnn_kernel() {
    const int b = blockIdx.x;
    const int l = threadIdx.x;
    const int g = l & 3;               // all lanes mirror lanes 0-3 (uniform loads)
    const float vm = (g == 2) ? 1.0f : 0.5f;
    const float va = (g == 2) ? 0.0f : 0.5f;

    const float* ap = g_A + (size_t)b * NG + g * 8;
    const size_t ASTR = (size_t)BATCH * NG;   // floats per t-step

    float4 p0[16], p1[16];
#pragma unroll
    for (int q = 0; q < 16; q++) {
        p0[q] = *(const float4*)(ap + (size_t)q * ASTR);
        p1[q] = *(const float4*)(ap + (size_t)q * ASTR + 4);
    }
    float s = 0.f, c = 0.f;
    for (int t0 = 0; t0 < T_STEPS; t0 += 16) {
#pragma unroll
        for (int q = 0; q < 16; q++) {
            float4 A0 = p0[q], A1 = p1[q];
            int tn = t0 + 16 + q;
            if (tn < T_STEPS) {
                p0[q] = *(const float4*)(ap + (size_t)tn * ASTR);
                p1[q] = *(const float4*)(ap + (size_t)tn * ASTR + 4);
            }
            // Estrin degree-7: coeffs a0..a7 = (A0.x,A0.y,A0.z,A0.w,A1.x,A1.y,A1.z,A1.w)
            float s2 = s * s, s4 = s2 * s2;
            float b0 = fmaf(A0.y, s, A0.x);
            float b1 = fmaf(A0.w, s, A0.z);
            float b2 = fmaf(A1.y, s, A1.x);
            float b3 = fmaf(A1.w, s, A1.z);
            float c0 = fmaf(b1, s2, b0);
            float c1 = fmaf(b3, s2, b2);
            float qv = fmaf(c1, s4, c0);
            float val = fmaf(vm, tanh_fast(qv), va);
            float f = __shfl_sync(0xffffffffu, val, 0);
            float i = __shfl_sync(0xffffffffu, val, 1);
            float u = __shfl_sync(0xffffffffu, val, 2);
            float o = __shfl_sync(0xffffffffu, val, 3);
            c = fmaf(f, c, i * u);
            s = o * tanh_fast(c);
            if (l == 0) g_S[(size_t)(t0 + q) * BATCH + b] = s;
        }
    }
    if (l == 0) g_S[(size_t)T_STEPS * BATCH + b] = c;   // final cell state
}

// ---------------- expand: broadcast g_S scalars into the [.,.,128] output ----------------
// rows 0..T*B-1: stacked; rows T*B..T*B+B-1: hx (= h[T-1]); next B rows: cx.
__global__ void __launch_bounds__(256) expand_kernel(float4* __restrict__ out) {
    const size_t idx = (size_t)blockIdx.x * 256 + threadIdx.x;  // float4 index
    const size_t row = idx >> 5;
    const int b  = (int)(row & (BATCH - 1));
    const int tt = (int)(row >> 9);
    size_t src = row;
    if (tt == T_STEPS)     src = (size_t)(T_STEPS - 1) * BATCH + b;  // hx
    else if (tt > T_STEPS) src = (size_t)T_STEPS * BATCH + b;        // cx
    const float s = __ldg(&g_S[src]);
    const float4 v = make_float4(s, s, s, s);
    __stcs(&out[idx], v);
}

extern "C" void kernel_launch(void* const* d_in, const int* in_sizes, int n_in,
                              void* d_out, int out_size) {
    const float* X  = (const float*)d_in[0];
    const float* Wf = (const float*)d_in[1];
    const float* bf = (const float*)d_in[2];
    const float* Wi = (const float*)d_in[3];
    const float* bi = (const float*)d_in[4];
    const float* Wu = (const float*)d_in[5];
    const float* bu = (const float*)d_in[6];
    const float* Wo = (const float*)d_in[7];
    const float* bo = (const float*)d_in[8];
    float* out = (float*)d_out;

    cudaFuncSetAttribute(gemm_kernel, cudaFuncAttributeMaxDynamicSharedMemorySize,
                         GEMM_SMEM_BYTES);

    init_kernel<<<1, 32>>>(Wf, Wi, Wu, Wo);
    gemm_kernel<<<(T_STEPS * BATCH) / 128, 256, GEMM_SMEM_BYTES>>>(
        X, Wf, bf, Wi, bi, Wu, bu, Wo, bo);
    rnn_kernel<<<BATCH, 32>>>();
    // (T+2)*B rows * 32 float4/row / 256 threads = 131200 blocks
    expand_kernel<<<((T_STEPS + 2) * BATCH * 32) / 256, 256>>>((float4*)out);
}